// round 11
// baseline (speedup 1.0000x reference)
#include <cuda_runtime.h>
#include <cstdint>

#define SEQ      512
#define BATCH    256
#define INSZ     64
#define HID      256
#define KTOT     320          // HID + INSZ fused contraction
#define WH_STRIDE 324         // padded row in floats (conflict-free LDS.128 with j = lane + 32*jj)
#define G        4            // batch elements per cluster
#define NWARP    8
#define NTHREADS 256
#define C4W      10           // float4 columns per warp (80 total / 8 warps)
#define RED_ROW  6            // u64 per (warp,j) row in reduction buffer (padded, 48B)

#define SMEM_FLOATS_WH  (128 * WH_STRIDE)   // 41472
#define SMEM_FLOATS_RHS (2 * G * KTOT)      // 2560 (double-buffered [h | x_t] rows)
#define RED_U64         (NWARP * 128 * RED_ROW) // 6144
#define SMEM_BYTES ((SMEM_FLOATS_WH + SMEM_FLOATS_RHS) * 4 + RED_U64 * 8 + 128 * 4) // 225792

__device__ __forceinline__ void fma2(unsigned long long& d, unsigned long long a, unsigned long long b) {
    asm("fma.rn.f32x2 %0, %1, %2, %0;" : "+l"(d) : "l"(a), "l"(b));
}
__device__ __forceinline__ void add2(unsigned long long& d, unsigned long long a) {
    asm("add.rn.f32x2 %0, %0, %1;" : "+l"(d) : "l"(a));
}

__global__ void __cluster_dims__(2, 1, 1) __launch_bounds__(NTHREADS, 1)
rnn_persistent_kernel(const float* __restrict__ x,  const float* __restrict__ Wx,
                      const float* __restrict__ bx, const float* __restrict__ Wh,
                      const float* __restrict__ bh, float* __restrict__ out)
{
    extern __shared__ float sm[];
    float* wh_s  = sm;                                   // [128][324] : cols 0..255 = Wh half, 256..319 = Wx half
    float* rhs_s = sm + SMEM_FLOATS_WH;                  // [2][G][320]: cols 0..255 = h (full), 256..319 = x_t
    unsigned long long* red_s = (unsigned long long*)(sm + SMEM_FLOATS_WH + SMEM_FLOATS_RHS); // [8][128][6]
    float* bsum_s = (float*)(red_s + RED_U64);           // [128] : bh + bx folded

    const int tid   = threadIdx.x;
    const int rank  = blockIdx.x & 1;          // CTA rank within cluster
    const int b0    = (blockIdx.x >> 1) * G;   // first batch element of this cluster
    const int jbase = rank * 128;              // this CTA owns hidden rows [jbase, jbase+128)

    // ---- one-time init: stage weight slab + biases + rhs buffer 0 ----
    for (int idx = tid; idx < 128 * KTOT; idx += NTHREADS) {
        int j = idx / KTOT;
        int k = idx - j * KTOT;
        int jg = jbase + j;
        float v = (k < HID) ? Wh[jg * HID + k] : Wx[jg * INSZ + (k - HID)];
        wh_s[j * WH_STRIDE + k] = v;
    }
    if (tid < 128) bsum_s[tid] = bh[jbase + tid] + bx[jbase + tid];
    for (int idx = tid; idx < G * KTOT; idx += NTHREADS) {
        int b = idx / KTOT;
        int k = idx - b * KTOT;
        rhs_s[idx] = (k < HID) ? 0.f : x[(size_t)(b0 + b) * INSZ + (k - HID)];  // h0 = 0, x at t=0
    }
    __syncthreads();
    asm volatile("barrier.cluster.arrive.aligned;" ::: "memory");
    asm volatile("barrier.cluster.wait.aligned;"   ::: "memory");

    const int w  = tid >> 5;
    const int l  = tid & 31;
    const int bb = tid >> 6;     // for x prefetch: batch lane
    const int xi = tid & 63;     // for x prefetch: input index

    float* out_last = out + (size_t)SEQ * BATCH * HID;

    for (int t = 0; t < SEQ; ++t) {
        const int cur = t & 1;
        const int nxt = cur ^ 1;

        // prefetch next timestep's x early (long-latency LDG, consumed at end of step)
        float xv = 0.f;
        if (t + 1 < SEQ)
            xv = x[(size_t)(t + 1) * BATCH * INSZ + (size_t)(b0 + bb) * INSZ + xi];

        // ---- K-split GEMM: warp w covers float4 columns [w*10, w*10+10) of K=320 ----
        const float* rcur = rhs_s + cur * (G * KTOT);
        unsigned long long acc[4][4];   // [jj][b], packed (even-k, odd-k) partial sums
        #pragma unroll
        for (int jj = 0; jj < 4; ++jj)
            #pragma unroll
            for (int b = 0; b < 4; ++b) acc[jj][b] = 0ull;

        const ulonglong2* wp[4];
        #pragma unroll
        for (int jj = 0; jj < 4; ++jj)
            wp[jj] = (const ulonglong2*)(wh_s + (l + 32 * jj) * WH_STRIDE) + w * C4W;
        const ulonglong2* rp[4];
        #pragma unroll
        for (int b = 0; b < 4; ++b)
            rp[b] = (const ulonglong2*)(rcur + b * KTOT) + w * C4W;

        #pragma unroll
        for (int it = 0; it < C4W; ++it) {
            ulonglong2 wv[4], hv[4];
            #pragma unroll
            for (int jj = 0; jj < 4; ++jj) wv[jj] = wp[jj][it];   // Wh[j][k..k+3], lane-conflict-free
            #pragma unroll
            for (int b = 0; b < 4; ++b)   hv[b] = rp[b][it];      // rhs[b][k..k+3], warp broadcast
            #pragma unroll
            for (int jj = 0; jj < 4; ++jj)
                #pragma unroll
                for (int b = 0; b < 4; ++b) {
                    fma2(acc[jj][b], wv[jj].x, hv[b].x);
                    fma2(acc[jj][b], wv[jj].y, hv[b].y);
                }
        }

        // ---- stash per-warp partials ----
        #pragma unroll
        for (int jj = 0; jj < 4; ++jj) {
            int j = l + 32 * jj;
            ulonglong2* p = (ulonglong2*)(red_s + (size_t)(w * 128 + j) * RED_ROW);
            ulonglong2 v;
            v.x = acc[jj][0]; v.y = acc[jj][1]; p[0] = v;
            v.x = acc[jj][2]; v.y = acc[jj][3]; p[1] = v;
        }
        __syncthreads();

        // ---- cross-warp K reduction + bias + tanh + h exchange + output ----
        float* rnext = rhs_s + nxt * (G * KTOT);
        #pragma unroll
        for (int rep = 0; rep < 2; ++rep) {
            int o = tid + rep * NTHREADS;        // 512 outputs = 128 j x 4 b
            int j = o >> 2;
            int b = o & 3;
            const unsigned long long* q = red_s + (size_t)j * RED_ROW + b;
            unsigned long long s2 = q[0];
            #pragma unroll
            for (int ww = 1; ww < NWARP; ++ww) add2(s2, q[(size_t)ww * 128 * RED_ROW]);
            float lo, hi;
            asm("mov.b64 {%0, %1}, %2;" : "=f"(lo), "=f"(hi) : "l"(s2));
            float h = tanhf(lo + hi + bsum_s[j]);

            int jg = jbase + j;
            int bg = b0 + b;
            // local half of next h
            rnext[b * KTOT + jg] = h;
            // push same value into peer CTA's rhs buffer (DSMEM)
            unsigned int la = (unsigned int)__cvta_generic_to_shared(&rnext[b * KTOT + jg]);
            unsigned int ra;
            asm("mapa.shared::cluster.u32 %0, %1, %2;" : "=r"(ra) : "r"(la), "r"(rank ^ 1));
            asm volatile("st.shared::cluster.f32 [%0], %1;" :: "r"(ra), "f"(h));
            // h_seq output
            out[(size_t)t * BATCH * HID + (size_t)bg * HID + jg] = h;
            if (t == SEQ - 1) out_last[(size_t)bg * HID + jg] = h;
        }
        // stage next timestep's x slice
        if (t + 1 < SEQ)
            rnext[bb * KTOT + HID + xi] = xv;

        // release local+remote stores, acquire peer's — one cluster barrier per step
        asm volatile("barrier.cluster.arrive.aligned;" ::: "memory");
        asm volatile("barrier.cluster.wait.aligned;"   ::: "memory");
    }
}

extern "C" void kernel_launch(void* const* d_in, const int* in_sizes, int n_in,
                              void* d_out, int out_size) {
    const float* x  = (const float*)d_in[0];
    const float* Wx = (const float*)d_in[1];
    const float* bx = (const float*)d_in[2];
    const float* Wh = (const float*)d_in[3];
    const float* bh = (const float*)d_in[4];
    float* out = (float*)d_out;
    (void)in_sizes; (void)n_in; (void)out_size;

    cudaFuncSetAttribute(rnn_persistent_kernel,
                         cudaFuncAttributeMaxDynamicSharedMemorySize, SMEM_BYTES);
    // 64 clusters of 2 CTAs (cluster dims baked via __cluster_dims__), 1 CTA/SM, single wave
    rnn_persistent_kernel<<<128, NTHREADS, SMEM_BYTES>>>(x, Wx, bx, Wh, bh, out);
}

// round 12
// speedup vs baseline: 1.4695x; 1.4695x over previous
#include <cuda_runtime.h>
#include <cstdint>

#define SEQ      512
#define BATCH    256
#define INSZ     64
#define HID      256
#define KTOT     320            // HID + INSZ fused contraction
#define G        4              // batch elements per cluster
#define NWARP    8
#define NTHREADS 256
#define C4W      10             // float4 columns per warp (80 total / 8 warps)
#define RED_ROW  5              // u64 per (warp,j) row — odd => conflict-free 64b banking

#define WH_FLOATS  (128 * KTOT)            // 40960 (init staging only)
#define RHS_FLOATS (2 * G * KTOT)          // 2560  (double-buffered [h | x_t])
#define RED_U64    (NWARP * 128 * RED_ROW) // 5120
#define SMEM_BYTES (WH_FLOATS*4 + RHS_FLOATS*4 + RED_U64*8 + 128*4 + 16)

__device__ __forceinline__ void fma2(unsigned long long& d, unsigned long long a, unsigned long long b) {
    asm("fma.rn.f32x2 %0, %1, %2, %0;" : "+l"(d) : "l"(a), "l"(b));
}
__device__ __forceinline__ void add2(unsigned long long& d, unsigned long long a) {
    asm("add.rn.f32x2 %0, %0, %1;" : "+l"(d) : "l"(a));
}

__global__ void __cluster_dims__(2, 1, 1) __launch_bounds__(NTHREADS, 1)
rnn_persistent_kernel(const float* __restrict__ x,  const float* __restrict__ Wx,
                      const float* __restrict__ bx, const float* __restrict__ Wh,
                      const float* __restrict__ bh, float* __restrict__ out)
{
    extern __shared__ float sm[];
    float* wh_s  = sm;                                    // init staging only
    float* rhs_s = sm + WH_FLOATS;                        // [2][G][320]
    unsigned long long* red_s = (unsigned long long*)(rhs_s + RHS_FLOATS); // [8][128][5]
    float* bsum_s = (float*)(red_s + RED_U64);            // [128]
    unsigned long long* mbar = (unsigned long long*)(bsum_s + 128);        // [2]

    const int tid   = threadIdx.x;
    const int rank  = blockIdx.x & 1;
    const int b0    = (blockIdx.x >> 1) * G;
    const int jbase = rank * 128;
    const int w     = tid >> 5;
    const int l     = tid & 31;

    // ---- one-time init: stage weights, biases, rhs buffer 0, mbarriers ----
    for (int idx = tid; idx < 128 * KTOT; idx += NTHREADS) {
        int j = idx / KTOT;
        int k = idx - j * KTOT;
        int jg = jbase + j;
        wh_s[idx] = (k < HID) ? Wh[jg * HID + k] : Wx[jg * INSZ + (k - HID)];
    }
    if (tid < 128) bsum_s[tid] = bh[jbase + tid] + bx[jbase + tid];
    for (int idx = tid; idx < G * KTOT; idx += NTHREADS) {
        int b = idx / KTOT;
        int k = idx - b * KTOT;
        rhs_s[idx] = (k < HID) ? 0.f : x[(size_t)(b0 + b) * INSZ + (k - HID)];
    }
    unsigned mb_s0 = (unsigned)__cvta_generic_to_shared(mbar);
    if (tid == 0) {
        asm volatile("mbarrier.init.shared.b64 [%0], 1;" :: "r"(mb_s0)     : "memory");
        asm volatile("mbarrier.init.shared.b64 [%0], 1;" :: "r"(mb_s0 + 8) : "memory");
    }
    __syncthreads();

    // ---- weights -> registers: lane holds rows j=l+32jj, K-chunk [40w, 40w+40) ----
    unsigned long long wreg[4][2 * C4W];   // 160 regs
    #pragma unroll
    for (int jj = 0; jj < 4; ++jj) {
        const unsigned long long* wr =
            (const unsigned long long*)(wh_s + (l + 32 * jj) * KTOT) + w * (2 * C4W);
        #pragma unroll
        for (int p = 0; p < 2 * C4W; ++p) wreg[jj][p] = wr[p];
    }
    asm volatile("barrier.cluster.arrive.aligned;" ::: "memory");
    asm volatile("barrier.cluster.wait.aligned;"   ::: "memory");

    const int jr    = tid & 127;    // gather: j index (coalesced STG)
    const int bhalf = tid >> 7;     // gather: b low bit
    const int bb    = tid >> 6;     // x prefetch: batch lane
    const int xi    = tid & 63;     // x prefetch: input index
    int ph0 = 0, ph1 = 0;           // mbarrier phases

    float* outt     = out;
    float* out_last = out + (size_t)SEQ * BATCH * HID;

    for (int t = 0; t < SEQ; ++t) {
        const int cur = t & 1;
        const int nxt = cur ^ 1;
        const unsigned mb_nxt = mb_s0 + nxt * 8;

        // post expectation for this step's incoming peer half (sole arrival = this)
        if (tid == 0)
            asm volatile("mbarrier.arrive.expect_tx.shared.b64 _, [%0], %1;"
                         :: "r"(mb_nxt), "r"(2048u) : "memory");

        // prefetch next timestep's x (consumed at end of step)
        float xv = 0.f;
        if (t + 1 < SEQ)
            xv = x[(size_t)(t + 1) * BATCH * INSZ + (size_t)(b0 + bb) * INSZ + xi];

        // ---- K-split GEMM with register-resident weights ----
        const ulonglong2* rc2 =
            (const ulonglong2*)(rhs_s + cur * (G * KTOT) + w * (4 * C4W));
        unsigned long long acc[4][4];
        #pragma unroll
        for (int jj = 0; jj < 4; ++jj)
            #pragma unroll
            for (int b = 0; b < 4; ++b) acc[jj][b] = 0ull;

        #pragma unroll
        for (int it = 0; it < C4W; ++it) {
            #pragma unroll
            for (int b = 0; b < 4; ++b) {
                ulonglong2 hv = rc2[b * (KTOT / 4) + it];   // warp-broadcast LDS.128
                #pragma unroll
                for (int jj = 0; jj < 4; ++jj) {
                    fma2(acc[jj][b], wreg[jj][2 * it],     hv.x);
                    fma2(acc[jj][b], wreg[jj][2 * it + 1], hv.y);
                }
            }
        }

        // ---- stash per-warp partials (odd u64 stride => conflict-free) ----
        #pragma unroll
        for (int jj = 0; jj < 4; ++jj) {
            unsigned long long* pr = red_s + (size_t)(w * 128 + l + 32 * jj) * RED_ROW;
            pr[0] = acc[jj][0]; pr[1] = acc[jj][1];
            pr[2] = acc[jj][2]; pr[3] = acc[jj][3];
        }
        __syncthreads();

        // ---- reduce + bias + tanh + exchange + output ----
        float* rnext = rhs_s + nxt * (G * KTOT);
        const unsigned rnext_s = (unsigned)__cvta_generic_to_shared(rnext);
        unsigned ra_mb;
        asm("mapa.shared::cluster.u32 %0, %1, %2;" : "=r"(ra_mb) : "r"(mb_nxt), "r"(rank ^ 1));

        #pragma unroll
        for (int rep = 0; rep < 2; ++rep) {
            const int b = bhalf | (rep << 1);
            const unsigned long long* q = red_s + (size_t)jr * RED_ROW + b;
            unsigned long long s2 = q[0];
            #pragma unroll
            for (int ww = 1; ww < NWARP; ++ww) add2(s2, q[(size_t)ww * 128 * RED_ROW]);
            float lo, hi;
            asm("mov.b64 {%0, %1}, %2;" : "=f"(lo), "=f"(hi) : "l"(s2));
            float z = lo + hi + bsum_s[jr];
            // tanh(z) = 1 - 2/(exp2(2z*log2e)+1)  (abs err ~1e-7, cancellation-safe)
            float ex;  asm("ex2.approx.f32 %0, %1;" : "=f"(ex)  : "f"(z * 2.885390081777927f));
            float rcp; asm("rcp.approx.f32 %0, %1;" : "=f"(rcp) : "f"(ex + 1.0f));
            float h = fmaf(-2.0f, rcp, 1.0f);

            const int jg = jbase + jr;
            const int bg = b0 + b;
            rnext[b * KTOT + jg] = h;                       // local half
            // push to peer's rnext with tx-tracked async store
            unsigned la = rnext_s + (unsigned)(b * KTOT + jg) * 4u;
            unsigned ra;
            asm("mapa.shared::cluster.u32 %0, %1, %2;" : "=r"(ra) : "r"(la), "r"(rank ^ 1));
            asm volatile("st.async.shared::cluster.mbarrier::complete_tx::bytes.b32 [%0], %1, [%2];"
                         :: "r"(ra), "f"(h), "r"(ra_mb) : "memory");
            outt[(size_t)bg * HID + jg] = h;                // coalesced 128B
            if (t == SEQ - 1) out_last[(size_t)bg * HID + jg] = h;
        }
        if (t + 1 < SEQ) rnext[bb * KTOT + HID + xi] = xv;  // stage next x
        outt += BATCH * HID;

        __syncthreads();   // local rnext/x stores + red_s reads complete

        // wait for peer's 2KB into rnext (replaces 490-cyc cluster barrier)
        {
            const int p = nxt ? ph1 : ph0;
            asm volatile(
                "{\n\t.reg .pred P;\n\t"
                "WAITL%=:\n\t"
                "mbarrier.try_wait.parity.acquire.cta.shared::cta.b64 P, [%0], %1, 0x989680;\n\t"
                "@P bra DONE%=;\n\t"
                "bra WAITL%=;\n\t"
                "DONE%=:\n\t}"
                :: "r"(mb_nxt), "r"(p) : "memory");
            if (nxt) ph1 ^= 1; else ph0 ^= 1;
        }
    }
}

extern "C" void kernel_launch(void* const* d_in, const int* in_sizes, int n_in,
                              void* d_out, int out_size) {
    const float* x  = (const float*)d_in[0];
    const float* Wx = (const float*)d_in[1];
    const float* bx = (const float*)d_in[2];
    const float* Wh = (const float*)d_in[3];
    const float* bh = (const float*)d_in[4];
    float* out = (float*)d_out;
    (void)in_sizes; (void)n_in; (void)out_size;

    cudaFuncSetAttribute(rnn_persistent_kernel,
                         cudaFuncAttributeMaxDynamicSharedMemorySize, SMEM_BYTES);
    rnn_persistent_kernel<<<128, NTHREADS, SMEM_BYTES>>>(x, Wx, bx, Wh, bh, out);
}

// round 13
// speedup vs baseline: 1.4821x; 1.0085x over previous
#include <cuda_runtime.h>
#include <cstdint>

#define SEQ      512
#define BATCH    256
#define INSZ     64
#define HID      256
#define KTOT     320            // HID + INSZ fused contraction
#define G        4              // batch elements per cluster
#define NTHREADS 512            // 16 warps: kw = w&7 (K-split 8), jh = w>>3 (j half)
#define KSPLIT   8
#define KW_F     40             // floats of K per warp (320/8)
#define C2W      10             // ulonglong2 (4-float) chunks per warp K-range
#define RED_ROW  5              // u64 per (j) row per kw-slab — odd => conflict-free

#define WH_FLOATS  (128 * KTOT)              // 40960 (init staging only)
#define RHS_FLOATS (2 * G * KTOT)            // 2560  (double-buffered [h | x_t])
#define RED_U64    (KSPLIT * 128 * RED_ROW)  // 5120
#define SMEM_BYTES (WH_FLOATS*4 + RHS_FLOATS*4 + RED_U64*8 + 128*4 + 16)

__device__ __forceinline__ void fma2(unsigned long long& d, unsigned long long a, unsigned long long b) {
    asm("fma.rn.f32x2 %0, %1, %2, %0;" : "+l"(d) : "l"(a), "l"(b));
}
__device__ __forceinline__ void add2(unsigned long long& d, unsigned long long a) {
    asm("add.rn.f32x2 %0, %0, %1;" : "+l"(d) : "l"(a));
}

__global__ void __cluster_dims__(2, 1, 1) __launch_bounds__(NTHREADS, 1)
rnn_persistent_kernel(const float* __restrict__ x,  const float* __restrict__ Wx,
                      const float* __restrict__ bx, const float* __restrict__ Wh,
                      const float* __restrict__ bh, float* __restrict__ out)
{
    extern __shared__ float sm[];
    float* wh_s  = sm;                                    // init staging only
    float* rhs_s = sm + WH_FLOATS;                        // [2][G][320]
    unsigned long long* red_s = (unsigned long long*)(rhs_s + RHS_FLOATS); // [8][128][5] u64
    float* bsum_s = (float*)(red_s + RED_U64);            // [128]
    unsigned long long* mbar = (unsigned long long*)(bsum_s + 128);        // [2]

    const int tid   = threadIdx.x;
    const int rank  = blockIdx.x & 1;
    const int b0    = (blockIdx.x >> 1) * G;
    const int jbase = rank * 128;
    const int w     = tid >> 5;
    const int l     = tid & 31;
    const int kw    = w & (KSPLIT - 1);     // K chunk [kw*40, kw*40+40)
    const int jh    = w >> 3;               // j half: rows [jh*64, jh*64+64)

    // ---- one-time init: stage weights, biases, rhs buffer 0, mbarriers ----
    for (int idx = tid; idx < 128 * KTOT; idx += NTHREADS) {
        int j = idx / KTOT;
        int k = idx - j * KTOT;
        int jg = jbase + j;
        wh_s[idx] = (k < HID) ? Wh[jg * HID + k] : Wx[jg * INSZ + (k - HID)];
    }
    if (tid < 128) bsum_s[tid] = bh[jbase + tid] + bx[jbase + tid];
    for (int idx = tid; idx < G * KTOT; idx += NTHREADS) {
        int b = idx / KTOT;
        int k = idx - b * KTOT;
        rhs_s[idx] = (k < HID) ? 0.f : x[(size_t)(b0 + b) * INSZ + (k - HID)];
    }
    unsigned mb_s0 = (unsigned)__cvta_generic_to_shared(mbar);
    if (tid == 0) {
        asm volatile("mbarrier.init.shared.b64 [%0], 1;" :: "r"(mb_s0)     : "memory");
        asm volatile("mbarrier.init.shared.b64 [%0], 1;" :: "r"(mb_s0 + 8) : "memory");
    }
    __syncthreads();

    // ---- weights -> registers: thread owns rows j = jh*64 + l + 32*jj, K [kw*40, +40) ----
    unsigned long long wreg[2][2 * C2W];   // 40 u64 = 80 regs
    #pragma unroll
    for (int jj = 0; jj < 2; ++jj) {
        const unsigned long long* wr =
            (const unsigned long long*)(wh_s + (jh * 64 + l + 32 * jj) * KTOT + kw * KW_F);
        #pragma unroll
        for (int p = 0; p < 2 * C2W; ++p) wreg[jj][p] = wr[p];
    }
    asm volatile("barrier.cluster.arrive.aligned;" ::: "memory");
    asm volatile("barrier.cluster.wait.aligned;"   ::: "memory");

    const int jr = tid & 127;       // epilogue: j index (coalesced, conflict-free)
    const int br = tid >> 7;        // epilogue: batch index
    const int bb = tid >> 6;        // x prefetch: batch lane (valid for tid<256)
    const int xi = tid & 63;        // x prefetch: input index
    int ph0 = 0, ph1 = 0;           // mbarrier phases

    float* outt     = out;
    float* out_last = out + (size_t)SEQ * BATCH * HID;

    for (int t = 0; t < SEQ; ++t) {
        const int cur = t & 1;
        const int nxt = cur ^ 1;
        const unsigned mb_nxt = mb_s0 + nxt * 8;

        if (tid == 0)
            asm volatile("mbarrier.arrive.expect_tx.shared.b64 _, [%0], %1;"
                         :: "r"(mb_nxt), "r"(2048u) : "memory");

        // prefetch next timestep's x (consumed at end of step)
        float xv = 0.f;
        if (t + 1 < SEQ && tid < G * INSZ)
            xv = x[(size_t)(t + 1) * BATCH * INSZ + (size_t)(b0 + bb) * INSZ + xi];

        // ---- GEMM: register weights x shared rhs (full-warp-broadcast LDS.128) ----
        const ulonglong2* rc2 =
            (const ulonglong2*)(rhs_s + cur * (G * KTOT) + kw * KW_F);
        unsigned long long acc[2][4];
        #pragma unroll
        for (int jj = 0; jj < 2; ++jj)
            #pragma unroll
            for (int b = 0; b < 4; ++b) acc[jj][b] = 0ull;

        #pragma unroll
        for (int it = 0; it < C2W; ++it) {
            #pragma unroll
            for (int b = 0; b < 4; ++b) {
                ulonglong2 hv = rc2[b * (KTOT / 4) + it];
                #pragma unroll
                for (int jj = 0; jj < 2; ++jj) {
                    fma2(acc[jj][b], wreg[jj][2 * it],     hv.x);
                    fma2(acc[jj][b], wreg[jj][2 * it + 1], hv.y);
                }
            }
        }

        // ---- stash partials: red[kw][j][b], lane stride 5 u64 => conflict-free ----
        #pragma unroll
        for (int jj = 0; jj < 2; ++jj) {
            unsigned long long* pr =
                red_s + (size_t)(kw * 128 + jh * 64 + l + 32 * jj) * RED_ROW;
            pr[0] = acc[jj][0]; pr[1] = acc[jj][1];
            pr[2] = acc[jj][2]; pr[3] = acc[jj][3];
        }
        __syncthreads();

        // ---- reduce(8) + bias + tanh + exchange + output: ONE output per thread ----
        float* rnext = rhs_s + nxt * (G * KTOT);
        {
            const unsigned long long* q = red_s + (size_t)jr * RED_ROW + br;
            unsigned long long s2 = q[0];
            #pragma unroll
            for (int ww = 1; ww < KSPLIT; ++ww) add2(s2, q[(size_t)ww * 128 * RED_ROW]);
            float lo, hi;
            asm("mov.b64 {%0, %1}, %2;" : "=f"(lo), "=f"(hi) : "l"(s2));
            float z = lo + hi + bsum_s[jr];
            // tanh(z) = 1 - 2/(exp2(2z*log2e)+1)
            float ex;  asm("ex2.approx.f32 %0, %1;" : "=f"(ex)  : "f"(z * 2.885390081777927f));
            float rcp; asm("rcp.approx.f32 %0, %1;" : "=f"(rcp) : "f"(ex + 1.0f));
            float h = fmaf(-2.0f, rcp, 1.0f);

            const int jg = jbase + jr;
            const int bg = b0 + br;
            rnext[br * KTOT + jg] = h;                      // local half
            unsigned la = (unsigned)__cvta_generic_to_shared(&rnext[br * KTOT + jg]);
            unsigned ra, ra_mb;
            asm("mapa.shared::cluster.u32 %0, %1, %2;" : "=r"(ra)    : "r"(la),     "r"(rank ^ 1));
            asm("mapa.shared::cluster.u32 %0, %1, %2;" : "=r"(ra_mb) : "r"(mb_nxt), "r"(rank ^ 1));
            asm volatile("st.async.shared::cluster.mbarrier::complete_tx::bytes.b32 [%0], %1, [%2];"
                         :: "r"(ra), "f"(h), "r"(ra_mb) : "memory");
            outt[(size_t)bg * HID + jg] = h;                // coalesced 128B
            if (t == SEQ - 1) out_last[(size_t)bg * HID + jg] = h;
        }
        if (t + 1 < SEQ && tid < G * INSZ)
            rnext[bb * KTOT + HID + xi] = xv;               // stage next x
        outt += BATCH * HID;

        __syncthreads();   // local rnext/x stores visible; red_s reads complete

        // wait for peer's 2KB into rnext
        {
            const int p = nxt ? ph1 : ph0;
            asm volatile(
                "{\n\t.reg .pred P;\n\t"
                "WAITL%=:\n\t"
                "mbarrier.try_wait.parity.acquire.cta.shared::cta.b64 P, [%0], %1, 0x989680;\n\t"
                "@P bra DONE%=;\n\t"
                "bra WAITL%=;\n\t"
                "DONE%=:\n\t}"
                :: "r"(mb_nxt), "r"(p) : "memory");
            if (nxt) ph1 ^= 1; else ph0 ^= 1;
        }
    }
}

extern "C" void kernel_launch(void* const* d_in, const int* in_sizes, int n_in,
                              void* d_out, int out_size) {
    const float* x  = (const float*)d_in[0];
    const float* Wx = (const float*)d_in[1];
    const float* bx = (const float*)d_in[2];
    const float* Wh = (const float*)d_in[3];
    const float* bh = (const float*)d_in[4];
    float* out = (float*)d_out;
    (void)in_sizes; (void)n_in; (void)out_size;

    cudaFuncSetAttribute(rnn_persistent_kernel,
                         cudaFuncAttributeMaxDynamicSharedMemorySize, SMEM_BYTES);
    rnn_persistent_kernel<<<128, NTHREADS, SMEM_BYTES>>>(x, Wx, bx, Wh, bh, out);
}

// round 14
// speedup vs baseline: 1.6017x; 1.0807x over previous
#include <cuda_runtime.h>
#include <cstdint>

#define SEQ      512
#define BATCH    256
#define INSZ     64
#define HID      256
#define KTOT     320            // reordered contraction: [x 64 | local h 128 | peer h 128]
#define G        4              // batch elements per cluster
#define NTHREADS 512            // 16 warps: kw = w&7 (K-split 8), jh = w>>3 (j half)
#define KSPLIT   8
#define KW_F     40             // floats of K per warp chunk
#define C2W      10             // ulonglong2 (4-float) chunks per warp K-range

#define WH_FLOATS  (128 * KTOT)              // 40960 (staging, init only)
#define RHS_FLOATS (2 * G * KTOT)            // 2560  (double-buffered rows of 320)
#define RED_U64    (KSPLIT * G * 128)        // 4096  red[kw][b][j], lane-stride-1 => conflict-free
#define SMEM_BYTES (WH_FLOATS*4 + RHS_FLOATS*4 + RED_U64*8 + 128*4 + 16)

// K-region offsets within an rhs row
#define K_X      0
#define K_LOC    64
#define K_PEER   192

__device__ __forceinline__ void fma2(unsigned long long& d, unsigned long long a, unsigned long long b) {
    asm("fma.rn.f32x2 %0, %1, %2, %0;" : "+l"(d) : "l"(a), "l"(b));
}
__device__ __forceinline__ void add2(unsigned long long& d, unsigned long long a) {
    asm("add.rn.f32x2 %0, %0, %1;" : "+l"(d) : "l"(a));
}

__global__ void __cluster_dims__(2, 1, 1) __launch_bounds__(NTHREADS, 1)
rnn_persistent_kernel(const float* __restrict__ x,  const float* __restrict__ Wx,
                      const float* __restrict__ bx, const float* __restrict__ Wh,
                      const float* __restrict__ bh, float* __restrict__ out)
{
    extern __shared__ float sm[];
    float* wh_s  = sm;                                    // staging only
    float* rhs_s = sm + WH_FLOATS;                        // [2][G][320]
    unsigned long long* red_s = (unsigned long long*)(rhs_s + RHS_FLOATS); // [8][4][128]
    float* bsum_s = (float*)(red_s + RED_U64);            // [128]
    unsigned long long* mbar = (unsigned long long*)(bsum_s + 128);        // [2]

    const int tid   = threadIdx.x;
    const int rank  = blockIdx.x & 1;
    const int b0    = (blockIdx.x >> 1) * G;
    const int jbase = rank * 128;           // our hidden rows (global)
    const int pbase = 128 - jbase;          // peer's hidden rows (global)
    const int w     = tid >> 5;
    const int l     = tid & 31;
    const int kw    = w & (KSPLIT - 1);     // K chunk [kw*40, kw*40+40) of reordered K
    const int jh    = w >> 3;               // j half within our 128 rows

    // ---- one-time init: stage weights in REORDERED K layout ----
    for (int idx = tid; idx < 128 * KTOT; idx += NTHREADS) {
        int j = idx / KTOT;
        int k = idx - j * KTOT;
        int jg = jbase + j;
        float v;
        if (k < K_LOC)        v = Wx[jg * INSZ + k];                    // x region
        else if (k < K_PEER)  v = Wh[jg * HID + jbase + (k - K_LOC)];   // local-h region
        else                  v = Wh[jg * HID + pbase + (k - K_PEER)];  // peer-h region
        wh_s[idx] = v;
    }
    if (tid < 128) bsum_s[tid] = bh[jbase + tid] + bx[jbase + tid];
    // rhs buffer 0: x at [0,64), h regions zero
    for (int idx = tid; idx < G * KTOT; idx += NTHREADS) {
        int b = idx / KTOT;
        int k = idx - b * KTOT;
        rhs_s[idx] = (k < K_LOC) ? x[(size_t)(b0 + b) * INSZ + k] : 0.f;
    }
    unsigned mb_s0 = (unsigned)__cvta_generic_to_shared(mbar);
    if (tid == 0) {
        asm volatile("mbarrier.init.shared.b64 [%0], 1;" :: "r"(mb_s0)     : "memory");
        asm volatile("mbarrier.init.shared.b64 [%0], 1;" :: "r"(mb_s0 + 8) : "memory");
    }
    __syncthreads();

    // ---- weights -> registers: rows j = jh*64 + l + 32*jj, K chunk [kw*40, +40) ----
    unsigned long long wreg[2][2 * C2W];   // 40 u64 = 80 regs
    #pragma unroll
    for (int jj = 0; jj < 2; ++jj) {
        const unsigned long long* wr =
            (const unsigned long long*)(wh_s + (jh * 64 + l + 32 * jj) * KTOT + kw * KW_F);
        #pragma unroll
        for (int p = 0; p < 2 * C2W; ++p) wreg[jj][p] = wr[p];
    }
    asm volatile("barrier.cluster.arrive.aligned;" ::: "memory");
    asm volatile("barrier.cluster.wait.aligned;"   ::: "memory");

    const int jr = tid & 127;       // epilogue: local j (coalesced STG runs of 128)
    const int br = tid >> 7;        // epilogue: batch index
    const int bb = tid >> 6;        // x prefetch: batch lane (tid<256)
    const int xi = tid & 63;        // x prefetch: input index
    int ph0 = 0, ph1 = 0;           // per-buffer mbarrier phases

    float* outt     = out;
    float* out_last = out + (size_t)SEQ * BATCH * HID;

    for (int t = 0; t < SEQ; ++t) {
        const int cur = t & 1;
        const int nxt = cur ^ 1;
        const unsigned mb_cur = mb_s0 + cur * 8;
        const unsigned mb_nxt = mb_s0 + nxt * 8;

        // post expectation for NEXT buffer's incoming peer half (this step's epilogue)
        if (tid == 0 && t + 1 < SEQ)
            asm volatile("mbarrier.arrive.expect_tx.shared.b64 _, [%0], %1;"
                         :: "r"(mb_nxt), "r"(2048u) : "memory");

        // prefetch next timestep's x (consumed at end of step)
        float xv = 0.f;
        if (t + 1 < SEQ && tid < G * INSZ)
            xv = x[(size_t)(t + 1) * BATCH * INSZ + (size_t)(b0 + bb) * INSZ + xi];

        // B-warps (K chunks touching peer h) wait for peer's h of step t-1.
        // A-warps (kw<4, K in [0,160) = x + local h) proceed immediately.
        if (kw >= 4 && t > 0) {
            const int p = cur ? ph1 : ph0;
            asm volatile(
                "{\n\t.reg .pred P;\n\t"
                "WAITL%=:\n\t"
                "mbarrier.try_wait.parity.acquire.cta.shared::cta.b64 P, [%0], %1, 0x989680;\n\t"
                "@P bra DONE%=;\n\t"
                "bra WAITL%=;\n\t"
                "DONE%=:\n\t}"
                :: "r"(mb_cur), "r"(p) : "memory");
        }
        if (t > 0) { if (cur) ph1 ^= 1; else ph0 ^= 1; }

        // ---- GEMM: register weights x shared rhs (full-warp-broadcast LDS.128) ----
        const ulonglong2* rc2 =
            (const ulonglong2*)(rhs_s + cur * (G * KTOT) + kw * KW_F);
        unsigned long long acc[2][4];
        #pragma unroll
        for (int jj = 0; jj < 2; ++jj)
            #pragma unroll
            for (int b = 0; b < 4; ++b) acc[jj][b] = 0ull;

        #pragma unroll
        for (int it = 0; it < C2W; ++it) {
            #pragma unroll
            for (int b = 0; b < 4; ++b) {
                ulonglong2 hv = rc2[b * (KTOT / 4) + it];
                #pragma unroll
                for (int jj = 0; jj < 2; ++jj) {
                    fma2(acc[jj][b], wreg[jj][2 * it],     hv.x);
                    fma2(acc[jj][b], wreg[jj][2 * it + 1], hv.y);
                }
            }
        }

        // ---- stash partials: red[kw][b][j], lane stride 1 u64 => conflict-free ----
        #pragma unroll
        for (int jj = 0; jj < 2; ++jj) {
            const int j = jh * 64 + l + 32 * jj;
            #pragma unroll
            for (int b = 0; b < 4; ++b)
                red_s[(size_t)(kw * 4 + b) * 128 + j] = acc[jj][b];
        }
        __syncthreads();

        // ---- reduce(8) + bias + tanh + exchange + output: ONE output per thread ----
        float* rnext = rhs_s + nxt * (G * KTOT);
        {
            const unsigned long long* q = red_s + (size_t)br * 128 + jr;
            unsigned long long s2 = q[0];
            #pragma unroll
            for (int ww = 1; ww < KSPLIT; ++ww) add2(s2, q[(size_t)ww * 512]);
            float lo, hi;
            asm("mov.b64 {%0, %1}, %2;" : "=f"(lo), "=f"(hi) : "l"(s2));
            float z = lo + hi + bsum_s[jr];
            // tanh(z) = 1 - 2/(exp2(2z*log2e)+1)
            float ex;  asm("ex2.approx.f32 %0, %1;" : "=f"(ex)  : "f"(z * 2.885390081777927f));
            float rcp; asm("rcp.approx.f32 %0, %1;" : "=f"(rcp) : "f"(ex + 1.0f));
            float h = fmaf(-2.0f, rcp, 1.0f);

            // remote first (longest latency): our h lands in peer's PEER region
            if (t + 1 < SEQ) {
                unsigned la = (unsigned)__cvta_generic_to_shared(&rnext[br * KTOT + K_PEER + jr]);
                unsigned ra, ra_mb;
                asm("mapa.shared::cluster.u32 %0, %1, %2;" : "=r"(ra)    : "r"(la),     "r"(rank ^ 1));
                asm("mapa.shared::cluster.u32 %0, %1, %2;" : "=r"(ra_mb) : "r"(mb_nxt), "r"(rank ^ 1));
                asm volatile("st.async.shared::cluster.mbarrier::complete_tx::bytes.b32 [%0], %1, [%2];"
                             :: "r"(ra), "f"(h), "r"(ra_mb) : "memory");
            }
            rnext[br * KTOT + K_LOC + jr] = h;              // our h -> our LOCAL region

            const int jg = jbase + jr;
            const int bg = b0 + br;
            outt[(size_t)bg * HID + jg] = h;                // coalesced 128B
            if (t == SEQ - 1) out_last[(size_t)bg * HID + jg] = h;
        }
        if (t + 1 < SEQ && tid < G * INSZ)
            rnext[bb * KTOT + K_X + xi] = xv;               // stage next x
        outt += BATCH * HID;

        __syncthreads();   // local rnext (h, x) visible to A-warps of step t+1
    }
}

extern "C" void kernel_launch(void* const* d_in, const int* in_sizes, int n_in,
                              void* d_out, int out_size) {
    const float* x  = (const float*)d_in[0];
    const float* Wx = (const float*)d_in[1];
    const float* bx = (const float*)d_in[2];
    const float* Wh = (const float*)d_in[3];
    const float* bh = (const float*)d_in[4];
    float* out = (float*)d_out;
    (void)in_sizes; (void)n_in; (void)out_size;

    cudaFuncSetAttribute(rnn_persistent_kernel,
                         cudaFuncAttributeMaxDynamicSharedMemorySize, SMEM_BYTES);
    rnn_persistent_kernel<<<128, NTHREADS, SMEM_BYTES>>>(x, Wx, bx, Wh, bh, out);
}